// round 14
// baseline (speedup 1.0000x reference)
#include <cuda_runtime.h>
#include <cuda_bf16.h>
#include <cstdint>
#include <cstddef>

// ---------------------------------------------------------------------------
// Net_3813930959289 round 12: warp-QUAD cooperative HMMA MLP (32x32 slices).
//  - 512 threads (16 warps = 4 quads) per block, 148 persistent blocks.
//  - each quad owns a 32-point tile; each warp computes all 32 rows x 32 cols
//    (acc 8x4 = 32 regs). LDSM/HMMA ratio 0.33 (was 0.42 at M16N64).
//  - quad sync via named barriers; no block barrier in main loop.
//  - weights bf16 hi/lo resident in smem; 3-term split (Ah*Wh+Ah*Wl+Al*Wh)
// ---------------------------------------------------------------------------

#define RES 512
#define EMB 32
#define HID 128
#define NTHR 512
#define GRID_FUSED 148

__device__ __align__(16) float g_planesT[3 * RES * RES * EMB];

// ---- smem byte offsets ------------------------------------------------------
#define OFF_WH0   0        // [128 j][32 k] bf16, stride 64B, swz ^(j&3)
#define OFF_WL0   8192
#define OFF_WH1   16384    // [128][128] bf16, stride 256B, swz ^(j&7)
#define OFF_WL1   49152
#define OFF_WH2   81920
#define OFF_WL2   114688
#define OFF_ACTH  147456   // 4 quads x [32 rows][256B] bf16, swz ^(r&7)
#define OFF_ACTL  180224
#define OFF_B0    212992
#define OFF_B1    213504
#define OFF_B2    214016
#define OFF_W3    214528
#define OFF_B3    215040
#define OFF_PART  215056   // 4 quads x 128 floats (warp partial dots)
#define SMEM_BYTES 217104

// ---------------- asm helpers ------------------------------------------------
__device__ __forceinline__ uint32_t smem_u32(const void* p) {
    uint32_t a;
    asm("{ .reg .u64 t; cvta.to.shared.u64 t, %1; cvt.u32.u64 %0, t; }"
        : "=r"(a) : "l"(p));
    return a;
}
__device__ __forceinline__ void ldsm_x4(uint32_t r[4], uint32_t addr) {
    asm volatile("ldmatrix.sync.aligned.m8n8.x4.shared.b16 {%0,%1,%2,%3}, [%4];"
        : "=r"(r[0]), "=r"(r[1]), "=r"(r[2]), "=r"(r[3]) : "r"(addr));
}
__device__ __forceinline__ void st32(uint32_t addr, uint32_t v) {
    asm volatile("st.shared.b32 [%0], %1;" :: "r"(addr), "r"(v));
}
__device__ __forceinline__ void mma2(float (&d)[4], const uint32_t (&a)[4],
                                     uint32_t b0, uint32_t b1) {
    asm volatile(
        "mma.sync.aligned.m16n8k16.row.col.f32.bf16.bf16.f32 "
        "{%0,%1,%2,%3}, {%4,%5,%6,%7}, {%8,%9}, {%0,%1,%2,%3};"
        : "+f"(d[0]), "+f"(d[1]), "+f"(d[2]), "+f"(d[3])
        : "r"(a[0]), "r"(a[1]), "r"(a[2]), "r"(a[3]), "r"(b0), "r"(b1));
}
__device__ __forceinline__ uint32_t packbf(float lo, float hi) {
    uint32_t r;
    asm("cvt.rn.bf16x2.f32 %0, %1, %2;" : "=r"(r) : "f"(hi), "f"(lo));
    return r;
}
__device__ __forceinline__ float bfr(float v) {
    return __bfloat162float(__float2bfloat16(v));
}
__device__ __forceinline__ void bar_quad(int quad) {
    asm volatile("bar.sync %0, 128;" :: "r"(quad + 1) : "memory");
}

// ---------------- transpose planes ------------------------------------------
__global__ void transpose_planes_kernel(const float* __restrict__ planes) {
    __shared__ float s[32][33];
    int b  = blockIdx.x;
    int xb = b & 15;
    int y  = (b >> 4) & 511;
    int p  = b >> 13;
    int t  = threadIdx.x;
#pragma unroll
    for (int r = 0; r < 4; r++) {
        int e = t + r * 256;
        int c = e >> 5;
        int x = e & 31;
        size_t src = ((((size_t)p * 32 + c) * RES + y) << 9) + (xb << 5) + x;
        s[c][x] = planes[src];
    }
    __syncthreads();
#pragma unroll
    for (int r = 0; r < 4; r++) {
        int e = t + r * 256;
        int x = e >> 5;
        int c = e & 31;
        size_t dst = (((size_t)p * RES + y) * RES + (xb << 5) + x) * EMB + c;
        g_planesT[dst] = s[c][x];
    }
}

// ---------------- per-layer GEMM: warp computes M=32 x N=32 slice -----------
// acc[i][4], i = rb*4 + ng*2 + j8 : rows rb*16+{g,g+8}, cols wq*32+ng*16+j8*8
template<int KC, int WSTRIDE, int WMASK>
__device__ __forceinline__ void run_layer(float (&acc)[8][4],
                                          uint32_t aH, uint32_t aL,
                                          uint32_t wHb, uint32_t wLb,
                                          int lane, int wq) {
    int rowoff = lane & 7;
    int arow   = rowoff + ((lane >> 3) & 1) * 8;  // A x4 lane->row mapping
    int kpA    = (lane >> 4) & 1;
    int brow   = rowoff + ((lane >> 4) & 1) * 8;  // B x4: tiles 2,3 = rows+8
    int bmB    = (lane >> 3) & 1;                 // B x4: tiles 1,3 = k-hi
    uint32_t aR0H = aH + (uint32_t)arow * 256u;
    uint32_t aR1H = aH + (uint32_t)(16 + arow) * 256u;
    uint32_t aR0L = aL + (uint32_t)arow * 256u;
    uint32_t aR1L = aL + (uint32_t)(16 + arow) * 256u;
    uint32_t bH0 = wHb + (uint32_t)(wq * 32 + brow) * WSTRIDE;
    uint32_t bH1 = bH0 + 16u * WSTRIDE;
    uint32_t bL0 = wLb + (uint32_t)(wq * 32 + brow) * WSTRIDE;
    uint32_t bL1 = bL0 + 16u * WSTRIDE;
#pragma unroll
    for (int kc = 0; kc < KC; kc++) {
        uint32_t ah0[4], ah1[4], al0[4], al1[4];
        uint32_t aoff = (uint32_t)((2 * kc + kpA) ^ rowoff) << 4;
        ldsm_x4(ah0, aR0H + aoff);
        ldsm_x4(ah1, aR1H + aoff);
        ldsm_x4(al0, aR0L + aoff);
        ldsm_x4(al1, aR1L + aoff);
        uint32_t bh0[4], bh1[4], bl0[4], bl1[4];
        uint32_t boff = (uint32_t)((2 * kc + bmB) ^ (rowoff & WMASK)) << 4;
        ldsm_x4(bh0, bH0 + boff);
        ldsm_x4(bh1, bH1 + boff);
        ldsm_x4(bl0, bL0 + boff);
        ldsm_x4(bl1, bL1 + boff);
        // term Ah*Wh (8 independent)
        mma2(acc[0], ah0, bh0[0], bh0[1]);
        mma2(acc[1], ah0, bh0[2], bh0[3]);
        mma2(acc[2], ah0, bh1[0], bh1[1]);
        mma2(acc[3], ah0, bh1[2], bh1[3]);
        mma2(acc[4], ah1, bh0[0], bh0[1]);
        mma2(acc[5], ah1, bh0[2], bh0[3]);
        mma2(acc[6], ah1, bh1[0], bh1[1]);
        mma2(acc[7], ah1, bh1[2], bh1[3]);
        // term Ah*Wl
        mma2(acc[0], ah0, bl0[0], bl0[1]);
        mma2(acc[1], ah0, bl0[2], bl0[3]);
        mma2(acc[2], ah0, bl1[0], bl1[1]);
        mma2(acc[3], ah0, bl1[2], bl1[3]);
        mma2(acc[4], ah1, bl0[0], bl0[1]);
        mma2(acc[5], ah1, bl0[2], bl0[3]);
        mma2(acc[6], ah1, bl1[0], bl1[1]);
        mma2(acc[7], ah1, bl1[2], bl1[3]);
        // term Al*Wh
        mma2(acc[0], al0, bh0[0], bh0[1]);
        mma2(acc[1], al0, bh0[2], bh0[3]);
        mma2(acc[2], al0, bh1[0], bh1[1]);
        mma2(acc[3], al0, bh1[2], bh1[3]);
        mma2(acc[4], al1, bh0[0], bh0[1]);
        mma2(acc[5], al1, bh0[2], bh0[3]);
        mma2(acc[6], al1, bh1[0], bh1[1]);
        mma2(acc[7], al1, bh1[2], bh1[3]);
    }
}

__device__ __forceinline__ void acc_init(float (&acc)[8][4],
                                         const float* __restrict__ bias,
                                         int lane, int wq) {
    int t2 = (lane & 3) * 2;
#pragma unroll
    for (int i = 0; i < 8; i++) {
        float2 bv = *(const float2*)(bias + wq * 32 + (i & 3) * 8 + t2);
        acc[i][0] = bv.x; acc[i][1] = bv.y;
        acc[i][2] = bv.x; acc[i][3] = bv.y;
    }
}

// relu + bf16 hi/lo split + store cols [wq*32, wq*32+32) of 32 act rows
__device__ __forceinline__ void epi(float (&acc)[8][4],
                                    uint32_t aH, uint32_t aL,
                                    int lane, int wq) {
    int g = lane >> 2, t = lane & 3;
#pragma unroll
    for (int i = 0; i < 8; i++) {
        int rb = i >> 2;
        float v0 = fmaxf(acc[i][0], 0.f), v1 = fmaxf(acc[i][1], 0.f);
        float v2 = fmaxf(acc[i][2], 0.f), v3 = fmaxf(acc[i][3], 0.f);
        uint32_t swz = (uint32_t)((wq * 4 + (i & 3)) ^ g) << 4;
        uint32_t r0 = (uint32_t)(rb * 16 + g) * 256u + (uint32_t)t * 4u + swz;
        uint32_t r1 = r0 + 8u * 256u;
        st32(aH + r0, packbf(v0, v1));
        st32(aL + r0, packbf(v0 - bfr(v0), v1 - bfr(v1)));
        st32(aH + r1, packbf(v2, v3));
        st32(aL + r1, packbf(v2 - bfr(v2), v3 - bfr(v3)));
    }
}

// ---------------- fused kernel ----------------------------------------------
__global__ void __launch_bounds__(NTHR, 1)
fused_kernel(const float* __restrict__ coords,
             const float* __restrict__ w0, const float* __restrict__ b0,
             const float* __restrict__ w1, const float* __restrict__ b1,
             const float* __restrict__ w2, const float* __restrict__ b2,
             const float* __restrict__ w3, const float* __restrict__ b3,
             float* __restrict__ out, int N) {
    extern __shared__ char sm[];
    uint32_t smb = smem_u32(sm);
    int t    = threadIdx.x;
    int wid  = t >> 5;
    int lane = t & 31;
    int quad = wid >> 2;
    int wq   = wid & 3;

    // ---- one-time: split weights to bf16 hi/lo, swizzled for ldmatrix ----
    for (int i = t; i < HID * EMB; i += NTHR) {     // w0 [j][32]
        int j = i >> 5, k = i & 31;
        float v = __ldg(w0 + i);
        float h = bfr(v);
        uint32_t off = (uint32_t)j * 64u + (uint32_t)(((k >> 3) ^ (j & 3)) << 4)
                       + (uint32_t)((k & 7) * 2);
        *(__nv_bfloat16*)(sm + OFF_WH0 + off) = __float2bfloat16(v);
        *(__nv_bfloat16*)(sm + OFF_WL0 + off) = __float2bfloat16(v - h);
    }
    for (int i = t; i < HID * HID; i += NTHR) {     // w1, w2 [j][128]
        int j = i >> 7, k = i & 127;
        uint32_t off = (uint32_t)j * 256u + (uint32_t)(((k >> 3) ^ (j & 7)) << 4)
                       + (uint32_t)((k & 7) * 2);
        float v1 = __ldg(w1 + i);
        float h1 = bfr(v1);
        *(__nv_bfloat16*)(sm + OFF_WH1 + off) = __float2bfloat16(v1);
        *(__nv_bfloat16*)(sm + OFF_WL1 + off) = __float2bfloat16(v1 - h1);
        float v2 = __ldg(w2 + i);
        float h2 = bfr(v2);
        *(__nv_bfloat16*)(sm + OFF_WH2 + off) = __float2bfloat16(v2);
        *(__nv_bfloat16*)(sm + OFF_WL2 + off) = __float2bfloat16(v2 - h2);
    }
    if (t < HID) {
        ((float*)(sm + OFF_B0))[t] = __ldg(b0 + t);
        ((float*)(sm + OFF_B1))[t] = __ldg(b1 + t);
        ((float*)(sm + OFF_B2))[t] = __ldg(b2 + t);
        ((float*)(sm + OFF_W3))[t] = __ldg(w3 + t);
    }
    if (t == 0) *(float*)(sm + OFF_B3) = __ldg(b3);
    __syncthreads();

    const float* b0s = (const float*)(sm + OFF_B0);
    const float* b1s = (const float*)(sm + OFF_B1);
    const float* b2s = (const float*)(sm + OFF_B2);
    const float* w3s = (const float*)(sm + OFF_W3);
    float* parts     = (float*)(sm + OFF_PART) + quad * 128;
    const float b3v  = *(const float*)(sm + OFF_B3);

    uint32_t actH = smb + OFF_ACTH + (uint32_t)quad * 8192u;  // 32 rows x 256B
    uint32_t actL = smb + OFF_ACTL + (uint32_t)quad * 8192u;
    uint32_t wh0 = smb + OFF_WH0, wl0 = smb + OFF_WL0;
    uint32_t wh1 = smb + OFF_WH1, wl1 = smb + OFF_WL1;
    uint32_t wh2 = smb + OFF_WH2, wl2 = smb + OFF_WL2;

    int gquad  = blockIdx.x * 4 + quad;
    int stride = gridDim.x * 4;
    int numT   = (N + 31) >> 5;

    int g4 = lane >> 3, sub = lane & 7;

    for (int tile = gquad; tile < numT; tile += stride) {
        int base = tile << 5;

        // ---- Phase A: lanes 0..7 compute texel data for this warp's 8 pts --
        int   mm[3];
        float wxv[3], wyv[3];
        {
            int pt = base + wq * 8 + lane;
            bool ok = (lane < 8) && (pt < N);
            float cx = 0.f, cy = 0.f, cz = 0.f;
            if (ok) {
                cx = coords[3 * pt + 0];
                cy = coords[3 * pt + 1];
                cz = coords[3 * pt + 2];
            }
#pragma unroll
            for (int p = 0; p < 3; p++) {
                float sx = (p == 0) ? cx : ((p == 1) ? cy : cx);
                float sy = (p == 0) ? cy : ((p == 1) ? cz : cz);
                int ix0 = 4000, iy0 = 4000;
                float wx1 = 0.f, wy1 = 0.f;
                if (ok) {
                    float x = (sx + 1.0f) * 0.5f * (float)(RES - 1);
                    float y = (sy + 1.0f) * 0.5f * (float)(RES - 1);
                    float fx = floorf(x), fy = floorf(y);
                    ix0 = (int)fx; iy0 = (int)fy;
                    wx1 = x - fx;  wy1 = y - fy;
                }
                mm[p]  = (iy0 << 16) | (ix0 & 0xFFFF);
                wxv[p] = wx1;
                wyv[p] = wy1;
            }
        }

        // ---- Phase B: gather warp's 8 points (2 passes x 4 points) ----
        __syncwarp();
#pragma unroll
        for (int pass = 0; pass < 2; pass++) {
            int src = pass * 4 + g4;        // source lane (0..7)
            float4 a4 = make_float4(0.f, 0.f, 0.f, 0.f);
#pragma unroll
            for (int p = 0; p < 3; p++) {
                int   m   = __shfl_sync(0xffffffffu, mm[p],  src);
                float wx1 = __shfl_sync(0xffffffffu, wxv[p], src);
                float wy1 = __shfl_sync(0xffffffffu, wyv[p], src);
                int ix0 = (int)(short)(m & 0xFFFF);
                int iy0 = m >> 16;
                float wx0 = 1.0f - wx1, wy0 = 1.0f - wy1;
#pragma unroll
                for (int c = 0; c < 4; c++) {
                    int ix = ix0 + (c & 1);
                    int iy = iy0 + (c >> 1);
                    float wgt = ((c & 1) ? wx1 : wx0) * ((c >> 1) ? wy1 : wy0);
                    if ((unsigned)ix < (unsigned)RES && (unsigned)iy < (unsigned)RES) {
                        const float4* ptr =
                            (const float4*)(g_planesT +
                                ((((size_t)p * RES + iy) * RES + ix) << 5)) + sub;
                        float4 v = __ldg(ptr);
                        a4.x = fmaf(wgt, v.x, a4.x);
                        a4.y = fmaf(wgt, v.y, a4.y);
                        a4.z = fmaf(wgt, v.z, a4.z);
                        a4.w = fmaf(wgt, v.w, a4.w);
                    }
                }
            }
            int row = wq * 8 + pass * 4 + g4;   // act row 0..31
            uint32_t off = (uint32_t)row * 256u
                         + (uint32_t)(((sub >> 1) ^ (row & 7)) << 4)
                         + (uint32_t)((sub & 1) << 3);
            st32(actH + off,     packbf(a4.x, a4.y));
            st32(actH + off + 4, packbf(a4.z, a4.w));
            st32(actL + off,     packbf(a4.x - bfr(a4.x), a4.y - bfr(a4.y)));
            st32(actL + off + 4, packbf(a4.z - bfr(a4.z), a4.w - bfr(a4.w)));
        }
        bar_quad(quad);

        float acc[8][4];

        // ---- layer 1: K=32 ----
        acc_init(acc, b0s, lane, wq);
        run_layer<2, 64, 3>(acc, actH, actL, wh0, wl0, lane, wq);
        bar_quad(quad);                 // all reads done before epi writes
        epi(acc, actH, actL, lane, wq);
        bar_quad(quad);

        // ---- layer 2: K=128 ----
        acc_init(acc, b1s, lane, wq);
        run_layer<8, 256, 7>(acc, actH, actL, wh1, wl1, lane, wq);
        bar_quad(quad);
        epi(acc, actH, actL, lane, wq);
        bar_quad(quad);

        // ---- layer 3: K=128, fused output dot (partial over 32 j's) ----
        acc_init(acc, b2s, lane, wq);
        run_layer<8, 256, 7>(acc, actH, actL, wh2, wl2, lane, wq);
        {
            float sA = 0.f, sB = 0.f, sC = 0.f, sD = 0.f;
            int t2 = (lane & 3) * 2;
#pragma unroll
            for (int i = 0; i < 8; i++) {
                float2 wv = *(const float2*)(w3s + wq * 32 + (i & 3) * 8 + t2);
                float p0 = fmaxf(acc[i][0], 0.f) * wv.x + fmaxf(acc[i][1], 0.f) * wv.y;
                float p1 = fmaxf(acc[i][2], 0.f) * wv.x + fmaxf(acc[i][3], 0.f) * wv.y;
                if (i < 4) { sA += p0; sB += p1; }
                else       { sC += p0; sD += p1; }
            }
            sA += __shfl_xor_sync(0xffffffffu, sA, 1);
            sA += __shfl_xor_sync(0xffffffffu, sA, 2);
            sB += __shfl_xor_sync(0xffffffffu, sB, 1);
            sB += __shfl_xor_sync(0xffffffffu, sB, 2);
            sC += __shfl_xor_sync(0xffffffffu, sC, 1);
            sC += __shfl_xor_sync(0xffffffffu, sC, 2);
            sD += __shfl_xor_sync(0xffffffffu, sD, 1);
            sD += __shfl_xor_sync(0xffffffffu, sD, 2);
            if ((lane & 3) == 0) {
                int g = lane >> 2;
                parts[wq * 32 + g]      = sA;
                parts[wq * 32 + g + 8]  = sB;
                parts[wq * 32 + g + 16] = sC;
                parts[wq * 32 + g + 24] = sD;
            }
        }
        bar_quad(quad);
        if (wq == 0) {
            int g = base + lane;
            if (g < N)
                out[g] = parts[lane] + parts[32 + lane] +
                         parts[64 + lane] + parts[96 + lane] + b3v;
        }
        bar_quad(quad);   // protect parts + act reuse next tile
    }
}

// ---------------------------------------------------------------------------
extern "C" void kernel_launch(void* const* d_in, const int* in_sizes, int n_in,
                              void* d_out, int out_size) {
    const float* coords = (const float*)d_in[0];
    const float* planes = (const float*)d_in[1];
    const float* w0     = (const float*)d_in[2];
    const float* b0     = (const float*)d_in[3];
    const float* w1     = (const float*)d_in[4];
    const float* b1     = (const float*)d_in[5];
    const float* w2     = (const float*)d_in[6];
    const float* b2     = (const float*)d_in[7];
    const float* w3     = (const float*)d_in[8];
    const float* b3     = (const float*)d_in[9];
    float* out = (float*)d_out;

    int N = in_sizes[0] / 3;

    cudaFuncSetAttribute(fused_kernel,
                         cudaFuncAttributeMaxDynamicSharedMemorySize,
                         SMEM_BYTES);

    transpose_planes_kernel<<<3 * RES * (RES / 32), 256>>>(planes);
    fused_kernel<<<GRID_FUSED, NTHR, SMEM_BYTES>>>(coords, w0, b0, w1, b1,
                                                   w2, b2, w3, b3, out, N);
}

// round 16
// speedup vs baseline: 1.0538x; 1.0538x over previous
#include <cuda_runtime.h>
#include <cuda_fp16.h>
#include <cstdint>
#include <cstddef>

// ---------------------------------------------------------------------------
// Net_3813930959289 round 15: pair-cooperative HMMA MLP, fp16 2-term split.
//  - 512 threads (16 warps = 8 pairs) per block, 148 persistent blocks.
//  - each pair owns a 16-point tile; warp computes 16 rows x 64 cols (acc 32).
//  - W split to fp16 hi/lo (resident smem); A single fp16 (no residual buf).
//  - each layer: D = Ah*Wh + Ah*Wl  (fp32 accum; act quantization 2^-11/layer)
// ---------------------------------------------------------------------------

#define RES 512
#define EMB 32
#define HID 128
#define NTHR 512
#define GRID_FUSED 148

__device__ __align__(16) float g_planesT[3 * RES * RES * EMB];

// ---- smem byte offsets ------------------------------------------------------
#define OFF_WH0   0        // [128 j][32 k] fp16, stride 64B, swz ^(j&3)
#define OFF_WL0   8192
#define OFF_WH1   16384    // [128][128] fp16, stride 256B, swz ^(j&7)
#define OFF_WL1   49152
#define OFF_WH2   81920
#define OFF_WL2   114688
#define OFF_ACTH  147456   // 8 pairs x [16 rows][256B] fp16, swz ^(r&7)
#define OFF_B0    180224
#define OFF_B1    180736
#define OFF_B2    181248
#define OFF_W3    181760
#define OFF_B3    182272
#define OFF_PART  182288   // 8 pairs x 32 floats
#define SMEM_BYTES 183312

// ---------------- asm helpers ------------------------------------------------
__device__ __forceinline__ uint32_t smem_u32(const void* p) {
    uint32_t a;
    asm("{ .reg .u64 t; cvta.to.shared.u64 t, %1; cvt.u32.u64 %0, t; }"
        : "=r"(a) : "l"(p));
    return a;
}
__device__ __forceinline__ void ldsm_x4(uint32_t r[4], uint32_t addr) {
    asm volatile("ldmatrix.sync.aligned.m8n8.x4.shared.b16 {%0,%1,%2,%3}, [%4];"
        : "=r"(r[0]), "=r"(r[1]), "=r"(r[2]), "=r"(r[3]) : "r"(addr));
}
__device__ __forceinline__ void st32(uint32_t addr, uint32_t v) {
    asm volatile("st.shared.b32 [%0], %1;" :: "r"(addr), "r"(v));
}
__device__ __forceinline__ void mma2(float (&d)[4], const uint32_t (&a)[4],
                                     uint32_t b0, uint32_t b1) {
    asm volatile(
        "mma.sync.aligned.m16n8k16.row.col.f32.f16.f16.f32 "
        "{%0,%1,%2,%3}, {%4,%5,%6,%7}, {%8,%9}, {%0,%1,%2,%3};"
        : "+f"(d[0]), "+f"(d[1]), "+f"(d[2]), "+f"(d[3])
        : "r"(a[0]), "r"(a[1]), "r"(a[2]), "r"(a[3]), "r"(b0), "r"(b1));
}
// pack two fp32 -> f16x2 (lo arg in low half)
__device__ __forceinline__ uint32_t packf16(float lo, float hi) {
    uint32_t r;
    asm("cvt.rn.f16x2.f32 %0, %1, %2;" : "=r"(r) : "f"(hi), "f"(lo));
    return r;
}
__device__ __forceinline__ void bar_pair(int pair) {
    asm volatile("bar.sync %0, 64;" :: "r"(pair + 1) : "memory");
}

// ---------------- transpose planes ------------------------------------------
__global__ void transpose_planes_kernel(const float* __restrict__ planes) {
    __shared__ float s[32][33];
    int b  = blockIdx.x;
    int xb = b & 15;
    int y  = (b >> 4) & 511;
    int p  = b >> 13;
    int t  = threadIdx.x;
#pragma unroll
    for (int r = 0; r < 4; r++) {
        int e = t + r * 256;
        int c = e >> 5;
        int x = e & 31;
        size_t src = ((((size_t)p * 32 + c) * RES + y) << 9) + (xb << 5) + x;
        s[c][x] = planes[src];
    }
    __syncthreads();
#pragma unroll
    for (int r = 0; r < 4; r++) {
        int e = t + r * 256;
        int x = e >> 5;
        int c = e & 31;
        size_t dst = (((size_t)p * RES + y) * RES + (xb << 5) + x) * EMB + c;
        g_planesT[dst] = s[c][x];
    }
}

// ---------------- per-layer GEMM (warp computes N=64 slice) -----------------
// acc[8][4]: D rows 0..15 x j = nbase + np*16 + {0..15}
// per k-chunk: 1 A ldsm + 8 B ldsm, 16 HMMA (2-term fp16)
template<int KC, int WSTRIDE, int WMASK>
__device__ __forceinline__ void run_layer(float (&acc)[8][4],
                                          uint32_t aH,
                                          uint32_t wHb, uint32_t wLb,
                                          int lane) {
    int rowoff = lane & 7;
    int arow   = rowoff + ((lane >> 3) & 1) * 8;  // A x4 lane->row mapping
    int kpA    = (lane >> 4) & 1;
    int brow   = rowoff + ((lane >> 4) & 1) * 8;  // B x4: tiles 2,3 = rows+8
    int bmB    = (lane >> 3) & 1;                 // B x4: tiles 1,3 = k-hi
    uint32_t aRowH = aH + (uint32_t)arow * 256u;
    uint32_t bRowH = wHb + (uint32_t)brow * WSTRIDE;
    uint32_t bRowL = wLb + (uint32_t)brow * WSTRIDE;
#pragma unroll
    for (int kc = 0; kc < KC; kc++) {
        uint32_t ah[4];
        uint32_t aoff = (uint32_t)((2 * kc + kpA) ^ rowoff) << 4;
        ldsm_x4(ah, aRowH + aoff);
        uint32_t boff = (uint32_t)((2 * kc + bmB) ^ (rowoff & WMASK)) << 4;
#pragma unroll
        for (int np = 0; np < 4; np++) {
            uint32_t bh[4], bl[4];
            uint32_t nb = (uint32_t)(np * 16 * WSTRIDE) + boff;
            ldsm_x4(bh, bRowH + nb);
            ldsm_x4(bl, bRowL + nb);
            mma2(acc[2 * np],     ah, bh[0], bh[1]);
            mma2(acc[2 * np + 1], ah, bh[2], bh[3]);
            mma2(acc[2 * np],     ah, bl[0], bl[1]);
            mma2(acc[2 * np + 1], ah, bl[2], bl[3]);
        }
    }
}

__device__ __forceinline__ void acc_init(float (&acc)[8][4],
                                         const float* __restrict__ bias,
                                         int lane, int nbase) {
    int t2 = (lane & 3) * 2;
#pragma unroll
    for (int n = 0; n < 8; n++) {
        float2 bv = *(const float2*)(bias + nbase + n * 8 + t2);
        acc[n][0] = bv.x; acc[n][1] = bv.y;
        acc[n][2] = bv.x; acc[n][3] = bv.y;
    }
}

// relu + fp16 store to columns [nbase, nbase+64) of act rows
__device__ __forceinline__ void epi(float (&acc)[8][4],
                                    uint32_t aH, int lane, int wsub) {
    int g = lane >> 2, t = lane & 3;
    uint32_t rowA = (uint32_t)g * 256u + (uint32_t)t * 4u;
    uint32_t rowB = (uint32_t)(g + 8) * 256u + (uint32_t)t * 4u;
#pragma unroll
    for (int n = 0; n < 8; n++) {
        float v0 = fmaxf(acc[n][0], 0.f), v1 = fmaxf(acc[n][1], 0.f);
        float v2 = fmaxf(acc[n][2], 0.f), v3 = fmaxf(acc[n][3], 0.f);
        int chunk = n + 8 * wsub;   // 16B chunk index within 256B row
        uint32_t swz = (uint32_t)(chunk ^ g) << 4;
        st32(aH + rowA + swz, packf16(v0, v1));
        st32(aH + rowB + swz, packf16(v2, v3));
    }
}

// ---------------- fused kernel ----------------------------------------------
__global__ void __launch_bounds__(NTHR, 1)
fused_kernel(const float* __restrict__ coords,
             const float* __restrict__ w0, const float* __restrict__ b0,
             const float* __restrict__ w1, const float* __restrict__ b1,
             const float* __restrict__ w2, const float* __restrict__ b2,
             const float* __restrict__ w3, const float* __restrict__ b3,
             float* __restrict__ out, int N) {
    extern __shared__ char sm[];
    uint32_t smb = smem_u32(sm);
    int t    = threadIdx.x;
    int wid  = t >> 5;
    int lane = t & 31;
    int pair = wid >> 1;
    int wsub = wid & 1;
    int nbase = wsub * 64;

    // ---- one-time: split weights to fp16 hi/lo, swizzled for ldmatrix ----
    for (int i = t; i < HID * EMB; i += NTHR) {     // w0 [j][32]
        int j = i >> 5, k = i & 31;
        float v = __ldg(w0 + i);
        __half h = __float2half_rn(v);
        uint32_t off = (uint32_t)j * 64u + (uint32_t)(((k >> 3) ^ (j & 3)) << 4)
                       + (uint32_t)((k & 7) * 2);
        *(__half*)(sm + OFF_WH0 + off) = h;
        *(__half*)(sm + OFF_WL0 + off) = __float2half_rn(v - __half2float(h));
    }
    for (int i = t; i < HID * HID; i += NTHR) {     // w1, w2 [j][128]
        int j = i >> 7, k = i & 127;
        uint32_t off = (uint32_t)j * 256u + (uint32_t)(((k >> 3) ^ (j & 7)) << 4)
                       + (uint32_t)((k & 7) * 2);
        float v1 = __ldg(w1 + i);
        __half h1 = __float2half_rn(v1);
        *(__half*)(sm + OFF_WH1 + off) = h1;
        *(__half*)(sm + OFF_WL1 + off) = __float2half_rn(v1 - __half2float(h1));
        float v2 = __ldg(w2 + i);
        __half h2 = __float2half_rn(v2);
        *(__half*)(sm + OFF_WH2 + off) = h2;
        *(__half*)(sm + OFF_WL2 + off) = __float2half_rn(v2 - __half2float(h2));
    }
    if (t < HID) {
        ((float*)(sm + OFF_B0))[t] = __ldg(b0 + t);
        ((float*)(sm + OFF_B1))[t] = __ldg(b1 + t);
        ((float*)(sm + OFF_B2))[t] = __ldg(b2 + t);
        ((float*)(sm + OFF_W3))[t] = __ldg(w3 + t);
    }
    if (t == 0) *(float*)(sm + OFF_B3) = __ldg(b3);
    __syncthreads();

    const float* b0s = (const float*)(sm + OFF_B0);
    const float* b1s = (const float*)(sm + OFF_B1);
    const float* b2s = (const float*)(sm + OFF_B2);
    const float* w3s = (const float*)(sm + OFF_W3);
    float* parts     = (float*)(sm + OFF_PART) + pair * 32;
    const float b3v  = *(const float*)(sm + OFF_B3);

    uint32_t actH = smb + OFF_ACTH + (uint32_t)pair * 4096u;  // 16 rows x 256B
    uint32_t wh0 = smb + OFF_WH0, wl0 = smb + OFF_WL0;
    uint32_t wh1 = smb + OFF_WH1, wl1 = smb + OFF_WL1;
    uint32_t wh2 = smb + OFF_WH2, wl2 = smb + OFF_WL2;

    int gpair  = blockIdx.x * 8 + pair;
    int stride = gridDim.x * 8;
    int numT   = (N + 15) >> 4;

    int g4 = lane >> 3, sub = lane & 7;

    for (int tile = gpair; tile < numT; tile += stride) {
        int base = tile << 4;

        // ---- Phase A: lanes 0..15 compute per-point texel data (both warps)
        int   mm[3];
        float wxv[3], wyv[3];
        {
            int pt = base + lane;
            bool ok = (lane < 16) && (pt < N);
            float cx = 0.f, cy = 0.f, cz = 0.f;
            if (ok) {
                cx = coords[3 * pt + 0];
                cy = coords[3 * pt + 1];
                cz = coords[3 * pt + 2];
            }
#pragma unroll
            for (int p = 0; p < 3; p++) {
                float sx = (p == 0) ? cx : ((p == 1) ? cy : cx);
                float sy = (p == 0) ? cy : ((p == 1) ? cz : cz);
                int ix0 = 4000, iy0 = 4000;
                float wx1 = 0.f, wy1 = 0.f;
                if (ok) {
                    float x = (sx + 1.0f) * 0.5f * (float)(RES - 1);
                    float y = (sy + 1.0f) * 0.5f * (float)(RES - 1);
                    float fx = floorf(x), fy = floorf(y);
                    ix0 = (int)fx; iy0 = (int)fy;
                    wx1 = x - fx;  wy1 = y - fy;
                }
                mm[p]  = (iy0 << 16) | (ix0 & 0xFFFF);
                wxv[p] = wx1;
                wyv[p] = wy1;
            }
        }

        // ---- Phase B: gather. warp a -> points 0..7, warp b -> 8..15 ----
        __syncwarp();
#pragma unroll
        for (int rr = 0; rr < 2; rr++) {
            int r   = 2 * wsub + rr;
            int src = r * 4 + g4;       // local point 0..15
            float4 a4 = make_float4(0.f, 0.f, 0.f, 0.f);
#pragma unroll
            for (int p = 0; p < 3; p++) {
                int   m   = __shfl_sync(0xffffffffu, mm[p],  src);
                float wx1 = __shfl_sync(0xffffffffu, wxv[p], src);
                float wy1 = __shfl_sync(0xffffffffu, wyv[p], src);
                int ix0 = (int)(short)(m & 0xFFFF);
                int iy0 = m >> 16;
                float wx0 = 1.0f - wx1, wy0 = 1.0f - wy1;
#pragma unroll
                for (int c = 0; c < 4; c++) {
                    int ix = ix0 + (c & 1);
                    int iy = iy0 + (c >> 1);
                    float wgt = ((c & 1) ? wx1 : wx0) * ((c >> 1) ? wy1 : wy0);
                    if ((unsigned)ix < (unsigned)RES && (unsigned)iy < (unsigned)RES) {
                        const float4* ptr =
                            (const float4*)(g_planesT +
                                ((((size_t)p * RES + iy) * RES + ix) << 5)) + sub;
                        float4 v = __ldg(ptr);
                        a4.x = fmaf(wgt, v.x, a4.x);
                        a4.y = fmaf(wgt, v.y, a4.y);
                        a4.z = fmaf(wgt, v.z, a4.z);
                        a4.w = fmaf(wgt, v.w, a4.w);
                    }
                }
            }
            int row = r * 4 + g4;
            uint32_t off = (uint32_t)row * 256u
                         + (uint32_t)(((sub >> 1) ^ (row & 7)) << 4)
                         + (uint32_t)((sub & 1) << 3);
            st32(actH + off,     packf16(a4.x, a4.y));
            st32(actH + off + 4, packf16(a4.z, a4.w));
        }
        bar_pair(pair);

        float acc[8][4];

        // ---- layer 1: K=32 ----
        acc_init(acc, b0s, lane, nbase);
        run_layer<2, 64, 3>(acc, actH,
                            wh0 + (uint32_t)nbase * 64u,
                            wl0 + (uint32_t)nbase * 64u, lane);
        bar_pair(pair);                 // reads done before epi writes
        epi(acc, actH, lane, wsub);
        bar_pair(pair);

        // ---- layer 2: K=128 ----
        acc_init(acc, b1s, lane, nbase);
        run_layer<8, 256, 7>(acc, actH,
                             wh1 + (uint32_t)nbase * 256u,
                             wl1 + (uint32_t)nbase * 256u, lane);
        bar_pair(pair);
        epi(acc, actH, lane, wsub);
        bar_pair(pair);

        // ---- layer 3: K=128, fused output dot (partial over 64 j's) ----
        acc_init(acc, b2s, lane, nbase);
        run_layer<8, 256, 7>(acc, actH,
                             wh2 + (uint32_t)nbase * 256u,
                             wl2 + (uint32_t)nbase * 256u, lane);
        {
            float s0 = 0.f, s1 = 0.f;
            int t2 = (lane & 3) * 2;
#pragma unroll
            for (int n = 0; n < 8; n++) {
                float2 wv = *(const float2*)(w3s + nbase + n * 8 + t2);
                s0 += fmaxf(acc[n][0], 0.f) * wv.x + fmaxf(acc[n][1], 0.f) * wv.y;
                s1 += fmaxf(acc[n][2], 0.f) * wv.x + fmaxf(acc[n][3], 0.f) * wv.y;
            }
            s0 += __shfl_xor_sync(0xffffffffu, s0, 1);
            s0 += __shfl_xor_sync(0xffffffffu, s0, 2);
            s1 += __shfl_xor_sync(0xffffffffu, s1, 1);
            s1 += __shfl_xor_sync(0xffffffffu, s1, 2);
            if ((lane & 3) == 0) {
                int g = lane >> 2;
                parts[wsub * 16 + g]     = s0;
                parts[wsub * 16 + g + 8] = s1;
            }
        }
        bar_pair(pair);
        if (wsub == 0 && lane < 16) {
            int g = base + lane;
            if (g < N) out[g] = parts[lane] + parts[16 + lane] + b3v;
        }
        bar_pair(pair);   // protect parts + act reuse next tile
    }
}

// ---------------------------------------------------------------------------
extern "C" void kernel_launch(void* const* d_in, const int* in_sizes, int n_in,
                              void* d_out, int out_size) {
    const float* coords = (const float*)d_in[0];
    const float* planes = (const float*)d_in[1];
    const float* w0     = (const float*)d_in[2];
    const float* b0     = (const float*)d_in[3];
    const float* w1     = (const float*)d_in[4];
    const float* b1     = (const float*)d_in[5];
    const float* w2     = (const float*)d_in[6];
    const float* b2     = (const float*)d_in[7];
    const float* w3     = (const float*)d_in[8];
    const float* b3     = (const float*)d_in[9];
    float* out = (float*)d_out;

    int N = in_sizes[0] / 3;

    cudaFuncSetAttribute(fused_kernel,
                         cudaFuncAttributeMaxDynamicSharedMemorySize,
                         SMEM_BYTES);

    transpose_planes_kernel<<<3 * RES * (RES / 32), 256>>>(planes);
    fused_kernel<<<GRID_FUSED, NTHR, SMEM_BYTES>>>(coords, w0, b0, w1, b1,
                                                   w2, b2, w3, b3, out, N);
}

// round 17
// speedup vs baseline: 1.2126x; 1.1507x over previous
#include <cuda_runtime.h>
#include <cuda_fp16.h>
#include <cstdint>
#include <cstddef>

// ---------------------------------------------------------------------------
// Net_3813930959289 round 17: quad-cooperative HMMA MLP, 24 warps, fp16 2-term
//  - 768 threads (24 warps = 6 quads) per block, 148 persistent blocks.
//  - quad owns a 16-point tile; each warp computes 16 rows x 32 cols
//    (acc 4x4 = 16 regs -> ~70 regs/thread -> 6 warps/SMSP).
//  - ping-pong act buffers: 4 named barriers per tile (was 8).
//  - W split fp16 hi/lo resident in smem; D = Ah*Wh + Ah*Wl (fp32 accum).
// ---------------------------------------------------------------------------

#define RES 512
#define EMB 32
#define HID 128
#define NTHR 768
#define NQUADS 6
#define GRID_FUSED 148

__device__ __align__(16) float g_planesT[3 * RES * RES * EMB];

// ---- smem byte offsets ------------------------------------------------------
#define OFF_WH0   0        // [128 j][32 k] fp16, stride 64B, swz ^(j&3)
#define OFF_WL0   8192
#define OFF_WH1   16384    // [128][128] fp16, stride 256B, swz ^(j&7)
#define OFF_WL1   49152
#define OFF_WH2   81920
#define OFF_WL2   114688
#define OFF_ACT   147456   // 6 quads x 2 bufs x [16 rows][256B] fp16
#define OFF_B0    196608
#define OFF_B1    197120
#define OFF_B2    197632
#define OFF_W3    198144
#define OFF_B3    198656
#define OFF_PART  198672   // 6 quads x 64 floats
#define SMEM_BYTES 200208

// ---------------- asm helpers ------------------------------------------------
__device__ __forceinline__ uint32_t smem_u32(const void* p) {
    uint32_t a;
    asm("{ .reg .u64 t; cvta.to.shared.u64 t, %1; cvt.u32.u64 %0, t; }"
        : "=r"(a) : "l"(p));
    return a;
}
__device__ __forceinline__ void ldsm_x4(uint32_t r[4], uint32_t addr) {
    asm volatile("ldmatrix.sync.aligned.m8n8.x4.shared.b16 {%0,%1,%2,%3}, [%4];"
        : "=r"(r[0]), "=r"(r[1]), "=r"(r[2]), "=r"(r[3]) : "r"(addr));
}
__device__ __forceinline__ void st32(uint32_t addr, uint32_t v) {
    asm volatile("st.shared.b32 [%0], %1;" :: "r"(addr), "r"(v));
}
__device__ __forceinline__ void mma2(float (&d)[4], const uint32_t (&a)[4],
                                     uint32_t b0, uint32_t b1) {
    asm volatile(
        "mma.sync.aligned.m16n8k16.row.col.f32.f16.f16.f32 "
        "{%0,%1,%2,%3}, {%4,%5,%6,%7}, {%8,%9}, {%0,%1,%2,%3};"
        : "+f"(d[0]), "+f"(d[1]), "+f"(d[2]), "+f"(d[3])
        : "r"(a[0]), "r"(a[1]), "r"(a[2]), "r"(a[3]), "r"(b0), "r"(b1));
}
// pack two fp32 -> f16x2 (lo arg in low half)
__device__ __forceinline__ uint32_t packf16(float lo, float hi) {
    uint32_t r;
    asm("cvt.rn.f16x2.f32 %0, %1, %2;" : "=r"(r) : "f"(hi), "f"(lo));
    return r;
}
__device__ __forceinline__ void bar_quad(int quad) {
    asm volatile("bar.sync %0, 128;" :: "r"(quad + 1) : "memory");
}

// ---------------- transpose planes ------------------------------------------
__global__ void transpose_planes_kernel(const float* __restrict__ planes) {
    __shared__ float s[32][33];
    int b  = blockIdx.x;
    int xb = b & 15;
    int y  = (b >> 4) & 511;
    int p  = b >> 13;
    int t  = threadIdx.x;
#pragma unroll
    for (int r = 0; r < 4; r++) {
        int e = t + r * 256;
        int c = e >> 5;
        int x = e & 31;
        size_t src = ((((size_t)p * 32 + c) * RES + y) << 9) + (xb << 5) + x;
        s[c][x] = planes[src];
    }
    __syncthreads();
#pragma unroll
    for (int r = 0; r < 4; r++) {
        int e = t + r * 256;
        int x = e >> 5;
        int c = e & 31;
        size_t dst = (((size_t)p * RES + y) * RES + (xb << 5) + x) * EMB + c;
        g_planesT[dst] = s[c][x];
    }
}

// ---------------- per-layer GEMM (warp computes M=16 x N=32 slice) ----------
// acc[ng][4]: rows {g, g+8} x cols nbase + ng*8 + {t*2, t*2+1}
// per k-chunk: 1 A ldsm + 4 B ldsm, 8 HMMA
template<int KC, int WSTRIDE, int WMASK>
__device__ __forceinline__ void run_layer(float (&acc)[4][4],
                                          uint32_t aIn,
                                          uint32_t wHb, uint32_t wLb,
                                          int lane) {
    int rowoff = lane & 7;
    int arow   = rowoff + ((lane >> 3) & 1) * 8;  // A x4 lane->row mapping
    int kpA    = (lane >> 4) & 1;
    int brow   = rowoff + ((lane >> 4) & 1) * 8;  // B x4: tiles 2,3 = rows+8
    int bmB    = (lane >> 3) & 1;                 // B x4: tiles 1,3 = k-hi
    uint32_t aRow = aIn + (uint32_t)arow * 256u;
    uint32_t bH = wHb + (uint32_t)brow * WSTRIDE;
    uint32_t bL = wLb + (uint32_t)brow * WSTRIDE;
#pragma unroll
    for (int kc = 0; kc < KC; kc++) {
        uint32_t ah[4];
        uint32_t aoff = (uint32_t)((2 * kc + kpA) ^ rowoff) << 4;
        ldsm_x4(ah, aRow + aoff);
        uint32_t boff = (uint32_t)((2 * kc + bmB) ^ (rowoff & WMASK)) << 4;
        uint32_t bh0[4], bh1[4], bl0[4], bl1[4];
        ldsm_x4(bh0, bH + boff);
        ldsm_x4(bh1, bH + (uint32_t)(16 * WSTRIDE) + boff);
        ldsm_x4(bl0, bL + boff);
        ldsm_x4(bl1, bL + (uint32_t)(16 * WSTRIDE) + boff);
        mma2(acc[0], ah, bh0[0], bh0[1]);
        mma2(acc[1], ah, bh0[2], bh0[3]);
        mma2(acc[2], ah, bh1[0], bh1[1]);
        mma2(acc[3], ah, bh1[2], bh1[3]);
        mma2(acc[0], ah, bl0[0], bl0[1]);
        mma2(acc[1], ah, bl0[2], bl0[3]);
        mma2(acc[2], ah, bl1[0], bl1[1]);
        mma2(acc[3], ah, bl1[2], bl1[3]);
    }
}

__device__ __forceinline__ void acc_init(float (&acc)[4][4],
                                         const float* __restrict__ bias,
                                         int lane, int nbase) {
    int t2 = (lane & 3) * 2;
#pragma unroll
    for (int n = 0; n < 4; n++) {
        float2 bv = *(const float2*)(bias + nbase + n * 8 + t2);
        acc[n][0] = bv.x; acc[n][1] = bv.y;
        acc[n][2] = bv.x; acc[n][3] = bv.y;
    }
}

// relu + fp16 store to columns [nbase, nbase+32) of out act rows
__device__ __forceinline__ void epi(float (&acc)[4][4],
                                    uint32_t aOut, int lane, int wq) {
    int g = lane >> 2, t = lane & 3;
    uint32_t rowA = (uint32_t)g * 256u + (uint32_t)t * 4u;
    uint32_t rowB = (uint32_t)(g + 8) * 256u + (uint32_t)t * 4u;
#pragma unroll
    for (int n = 0; n < 4; n++) {
        float v0 = fmaxf(acc[n][0], 0.f), v1 = fmaxf(acc[n][1], 0.f);
        float v2 = fmaxf(acc[n][2], 0.f), v3 = fmaxf(acc[n][3], 0.f);
        int chunk = wq * 4 + n;     // 16B chunk index within 256B row
        uint32_t swz = (uint32_t)(chunk ^ g) << 4;
        st32(aOut + rowA + swz, packf16(v0, v1));
        st32(aOut + rowB + swz, packf16(v2, v3));
    }
}

// ---------------- fused kernel ----------------------------------------------
__global__ void __launch_bounds__(NTHR, 1)
fused_kernel(const float* __restrict__ coords,
             const float* __restrict__ w0, const float* __restrict__ b0,
             const float* __restrict__ w1, const float* __restrict__ b1,
             const float* __restrict__ w2, const float* __restrict__ b2,
             const float* __restrict__ w3, const float* __restrict__ b3,
             float* __restrict__ out, int N) {
    extern __shared__ char sm[];
    uint32_t smb = smem_u32(sm);
    int t    = threadIdx.x;
    int wid  = t >> 5;
    int lane = t & 31;
    int quad = wid >> 2;           // 0..5
    int wq   = wid & 3;
    int nbase = wq * 32;

    // ---- one-time: split weights to fp16 hi/lo, swizzled for ldmatrix ----
    for (int i = t; i < HID * EMB; i += NTHR) {     // w0 [j][32]
        int j = i >> 5, k = i & 31;
        float v = __ldg(w0 + i);
        __half h = __float2half_rn(v);
        uint32_t off = (uint32_t)j * 64u + (uint32_t)(((k >> 3) ^ (j & 3)) << 4)
                       + (uint32_t)((k & 7) * 2);
        *(__half*)(sm + OFF_WH0 + off) = h;
        *(__half*)(sm + OFF_WL0 + off) = __float2half_rn(v - __half2float(h));
    }
    for (int i = t; i < HID * HID; i += NTHR) {     // w1, w2 [j][128]
        int j = i >> 7, k = i & 127;
        uint32_t off = (uint32_t)j * 256u + (uint32_t)(((k >> 3) ^ (j & 7)) << 4)
                       + (uint32_t)((k & 7) * 2);
        float v1 = __ldg(w1 + i);
        __half h1 = __float2half_rn(v1);
        *(__half*)(sm + OFF_WH1 + off) = h1;
        *(__half*)(sm + OFF_WL1 + off) = __float2half_rn(v1 - __half2float(h1));
        float v2 = __ldg(w2 + i);
        __half h2 = __float2half_rn(v2);
        *(__half*)(sm + OFF_WH2 + off) = h2;
        *(__half*)(sm + OFF_WL2 + off) = __float2half_rn(v2 - __half2float(h2));
    }
    if (t < HID) {
        ((float*)(sm + OFF_B0))[t] = __ldg(b0 + t);
        ((float*)(sm + OFF_B1))[t] = __ldg(b1 + t);
        ((float*)(sm + OFF_B2))[t] = __ldg(b2 + t);
        ((float*)(sm + OFF_W3))[t] = __ldg(w3 + t);
    }
    if (t == 0) *(float*)(sm + OFF_B3) = __ldg(b3);
    __syncthreads();

    const float* b0s = (const float*)(sm + OFF_B0);
    const float* b1s = (const float*)(sm + OFF_B1);
    const float* b2s = (const float*)(sm + OFF_B2);
    const float* w3s = (const float*)(sm + OFF_W3);
    float* parts     = (float*)(sm + OFF_PART) + quad * 64;
    const float b3v  = *(const float*)(sm + OFF_B3);

    uint32_t bufA = smb + OFF_ACT + (uint32_t)quad * 8192u;  // 16 rows x 256B
    uint32_t bufB = bufA + 4096u;
    uint32_t wh0 = smb + OFF_WH0, wl0 = smb + OFF_WL0;
    uint32_t wh1 = smb + OFF_WH1, wl1 = smb + OFF_WL1;
    uint32_t wh2 = smb + OFF_WH2, wl2 = smb + OFF_WL2;

    int gquad  = blockIdx.x * NQUADS + quad;
    int stride = gridDim.x * NQUADS;
    int numT   = (N + 15) >> 4;

    int g4 = lane >> 3, sub = lane & 7;

    for (int tile = gquad; tile < numT; tile += stride) {
        int base = tile << 4;

        // ---- Phase A: lanes 0..3 load coords for this warp's 4 points ----
        int   mm[3];
        float wxv[3], wyv[3];
        {
            int pt = base + wq * 4 + lane;
            bool ok = (lane < 4) && (pt < N);
            float cx = 0.f, cy = 0.f, cz = 0.f;
            if (ok) {
                cx = coords[3 * pt + 0];
                cy = coords[3 * pt + 1];
                cz = coords[3 * pt + 2];
            }
#pragma unroll
            for (int p = 0; p < 3; p++) {
                float sx = (p == 0) ? cx : ((p == 1) ? cy : cx);
                float sy = (p == 0) ? cy : ((p == 1) ? cz : cz);
                int ix0 = 4000, iy0 = 4000;
                float wx1 = 0.f, wy1 = 0.f;
                if (ok) {
                    float x = (sx + 1.0f) * 0.5f * (float)(RES - 1);
                    float y = (sy + 1.0f) * 0.5f * (float)(RES - 1);
                    float fx = floorf(x), fy = floorf(y);
                    ix0 = (int)fx; iy0 = (int)fy;
                    wx1 = x - fx;  wy1 = y - fy;
                }
                mm[p]  = (iy0 << 16) | (ix0 & 0xFFFF);
                wxv[p] = wx1;
                wyv[p] = wy1;
            }
        }

        // ---- Phase B: gather 4 points, 8 lanes each (one pass) ----
        __syncwarp();
        {
            int src = g4;               // source lane 0..3
            float4 a4 = make_float4(0.f, 0.f, 0.f, 0.f);
#pragma unroll
            for (int p = 0; p < 3; p++) {
                int   m   = __shfl_sync(0xffffffffu, mm[p],  src);
                float wx1 = __shfl_sync(0xffffffffu, wxv[p], src);
                float wy1 = __shfl_sync(0xffffffffu, wyv[p], src);
                int ix0 = (int)(short)(m & 0xFFFF);
                int iy0 = m >> 16;
                float wx0 = 1.0f - wx1, wy0 = 1.0f - wy1;
#pragma unroll
                for (int c = 0; c < 4; c++) {
                    int ix = ix0 + (c & 1);
                    int iy = iy0 + (c >> 1);
                    float wgt = ((c & 1) ? wx1 : wx0) * ((c >> 1) ? wy1 : wy0);
                    if ((unsigned)ix < (unsigned)RES && (unsigned)iy < (unsigned)RES) {
                        const float4* ptr =
                            (const float4*)(g_planesT +
                                ((((size_t)p * RES + iy) * RES + ix) << 5)) + sub;
                        float4 v = __ldg(ptr);
                        a4.x = fmaf(wgt, v.x, a4.x);
                        a4.y = fmaf(wgt, v.y, a4.y);
                        a4.z = fmaf(wgt, v.z, a4.z);
                        a4.w = fmaf(wgt, v.w, a4.w);
                    }
                }
            }
            int row = wq * 4 + g4;      // act row 0..15
            uint32_t off = (uint32_t)row * 256u
                         + (uint32_t)(((sub >> 1) ^ (row & 7)) << 4)
                         + (uint32_t)((sub & 1) << 3);
            st32(bufA + off,     packf16(a4.x, a4.y));
            st32(bufA + off + 4, packf16(a4.z, a4.w));
        }
        bar_quad(quad);                       // bar 1: feats ready in bufA

        float acc[4][4];

        // ---- layer 1: K=32, bufA -> bufB ----
        acc_init(acc, b0s, lane, nbase);
        run_layer<2, 64, 3>(acc, bufA,
                            wh0 + (uint32_t)nbase * 64u,
                            wl0 + (uint32_t)nbase * 64u, lane);
        epi(acc, bufB, lane, wq);
        bar_quad(quad);                       // bar 2: bufB ready

        // ---- layer 2: K=128, bufB -> bufA ----
        acc_init(acc, b1s, lane, nbase);
        run_layer<8, 256, 7>(acc, bufB,
                             wh1 + (uint32_t)nbase * 256u,
                             wl1 + (uint32_t)nbase * 256u, lane);
        epi(acc, bufA, lane, wq);
        bar_quad(quad);                       // bar 3: bufA ready

        // ---- layer 3: K=128, bufA -> partial dots ----
        acc_init(acc, b2s, lane, nbase);
        run_layer<8, 256, 7>(acc, bufA,
                             wh2 + (uint32_t)nbase * 256u,
                             wl2 + (uint32_t)nbase * 256u, lane);
        {
            float s0 = 0.f, s1 = 0.f;
            int t2 = (lane & 3) * 2;
#pragma unroll
            for (int n = 0; n < 4; n++) {
                float2 wv = *(const float2*)(w3s + nbase + n * 8 + t2);
                s0 += fmaxf(acc[n][0], 0.f) * wv.x + fmaxf(acc[n][1], 0.f) * wv.y;
                s1 += fmaxf(acc[n][2], 0.f) * wv.x + fmaxf(acc[n][3], 0.f) * wv.y;
            }
            s0 += __shfl_xor_sync(0xffffffffu, s0, 1);
            s0 += __shfl_xor_sync(0xffffffffu, s0, 2);
            s1 += __shfl_xor_sync(0xffffffffu, s1, 1);
            s1 += __shfl_xor_sync(0xffffffffu, s1, 2);
            if ((lane & 3) == 0) {
                int g = lane >> 2;
                parts[wq * 16 + g]     = s0;
                parts[wq * 16 + g + 8] = s1;
            }
        }
        bar_quad(quad);                       // bar 4: parts ready, L3 reads done
        if (wq == 0 && lane < 16) {
            int g = base + lane;
            if (g < N)
                out[g] = parts[lane] + parts[16 + lane] +
                         parts[32 + lane] + parts[48 + lane] + b3v;
        }
        // no trailing barrier needed: the next parts write for this quad is
        // 4 barriers away; wq0 passes the same barriers before then.
    }
}

// ---------------------------------------------------------------------------
extern "C" void kernel_launch(void* const* d_in, const int* in_sizes, int n_in,
                              void* d_out, int out_size) {
    const float* coords = (const float*)d_in[0];
    const float* planes = (const float*)d_in[1];
    const float* w0     = (const float*)d_in[2];
    const float* b0     = (const float*)d_in[3];
    const float* w1     = (const float*)d_in[4];
    const float* b1     = (const float*)d_in[5];
    const float* w2     = (const float*)d_in[6];
    const float* b2     = (const float*)d_in[7];
    const float* w3     = (const float*)d_in[8];
    const float* b3     = (const float*)d_in[9];
    float* out = (float*)d_out;

    int N = in_sizes[0] / 3;

    cudaFuncSetAttribute(fused_kernel,
                         cudaFuncAttributeMaxDynamicSharedMemorySize,
                         SMEM_BYTES);

    transpose_planes_kernel<<<3 * RES * (RES / 32), 256>>>(planes);
    fused_kernel<<<GRID_FUSED, NTHR, SMEM_BYTES>>>(coords, w0, b0, w1, b1,
                                                   w2, b2, w3, b3, out, N);
}